// round 8
// baseline (speedup 1.0000x reference)
#include <cuda_runtime.h>
#include <cuda_bf16.h>
#include <math.h>
#include <stdint.h>

// Problem dims (fixed by setup_inputs)
#define NB 8
#define NS 2048
#define DV 768
#define DA 512
#define NK 512
#define NR (NB*NS)            // 16384 rows
#define LAM 0.3f

// Fused GEMM tiling (mma.sync m16n8k16 bf16)
#define BM 128
#define BN 128
#define BK 32                 // bf16 k per chunk
#define NTH 512               // 16 warps, 4x4 warp grid, 32x32 warp tiles
#define ATILE 10240           // 128 rows * 80 B
#define STGB 20480            // one stage: A tile + B tile
#define NSTAGE 3
#define FUSED_SMEM (NSTAGE*STGB)   // 61440
#define NBLOCKS ((NK/BN)*(NR/BM)*2)   // 1024

// ---------------- device scratch; bf16 stored in uint4 arrays (16B-aligned) --
__device__ uint4 g_fV16u[(size_t)NR*DV/8];   // bf16 feat_vision
__device__ uint4 g_fA16u[(size_t)NR*DA/8];
__device__ uint4 g_sV16u[(size_t)NR*DV/8];   // bf16 smooth(feat_vision)
__device__ uint4 g_sA16u[(size_t)NR*DA/8];
__device__ uint4 g_pV16u[NK*DV/8];           // bf16 proto_vision
__device__ uint4 g_pA16u[NK*DA/8];
__device__ uint4 g_Mv16u[NK*DA/8];           // bf16 proto_v @ W_a2v
__device__ uint4 g_Ma16u[NK*DV/8];
__device__ float g_Mv[NK*DA];                // fp32 M (validated producer)
__device__ float g_Ma[NK*DV];
__device__ float g_partials[NBLOCKS];

#define G_FV16 ((__nv_bfloat16*)g_fV16u)
#define G_FA16 ((__nv_bfloat16*)g_fA16u)
#define G_SV16 ((__nv_bfloat16*)g_sV16u)
#define G_SA16 ((__nv_bfloat16*)g_sA16u)
#define G_PV16 ((__nv_bfloat16*)g_pV16u)
#define G_PA16 ((__nv_bfloat16*)g_pA16u)
#define G_MV16 ((__nv_bfloat16*)g_Mv16u)
#define G_MA16 ((__nv_bfloat16*)g_Ma16u)

// ---------------- helpers ----------------
__device__ __forceinline__ uint32_t smem_u32(const void* p) {
    uint32_t a;
    asm("{ .reg .u64 t; cvta.to.shared.u64 t, %1; cvt.u32.u64 %0, t; }" : "=r"(a) : "l"(p));
    return a;
}
__device__ __forceinline__ void cp16(uint32_t dst, const void* src) {
    asm volatile("cp.async.cg.shared.global [%0], [%1], 16;" :: "r"(dst), "l"(src) : "memory");
}
__device__ __forceinline__ void cp_commit() {
    asm volatile("cp.async.commit_group;" ::: "memory");
}
__device__ __forceinline__ void ldsm4(uint32_t* r, uint32_t addr) {
    asm volatile("ldmatrix.sync.aligned.m8n8.x4.shared.b16 {%0,%1,%2,%3}, [%4];"
                 : "=r"(r[0]), "=r"(r[1]), "=r"(r[2]), "=r"(r[3]) : "r"(addr));
}
__device__ __forceinline__ void ldsm2(uint32_t* r, uint32_t addr) {
    asm volatile("ldmatrix.sync.aligned.m8n8.x2.shared.b16 {%0,%1}, [%2];"
                 : "=r"(r[0]), "=r"(r[1]) : "r"(addr));
}
__device__ __forceinline__ void mma16816(float* c, const uint32_t* a, const uint32_t* b) {
    asm volatile(
        "mma.sync.aligned.m16n8k16.row.col.f32.bf16.bf16.f32 "
        "{%0,%1,%2,%3}, {%4,%5,%6,%7}, {%8,%9}, {%0,%1,%2,%3};"
        : "+f"(c[0]), "+f"(c[1]), "+f"(c[2]), "+f"(c[3])
        : "r"(a[0]), "r"(a[1]), "r"(a[2]), "r"(a[3]), "r"(b[0]), "r"(b[1]));
}
__device__ __forceinline__ uint2 cvt4(float4 v) {
    __nv_bfloat162 lo = __floats2bfloat162_rn(v.x, v.y);
    __nv_bfloat162 hi = __floats2bfloat162_rn(v.z, v.w);
    uint2 r;
    r.x = *reinterpret_cast<uint32_t*>(&lo);
    r.y = *reinterpret_cast<uint32_t*>(&hi);
    return r;
}

// ---------------------------------------------------------------------------
// R1-VALIDATED smooth computation + bf16 dual store (smooth + feat).
// which=1 -> vision, which=0 -> audio
// ---------------------------------------------------------------------------
__global__ void smooth_cvt2_kernel(const float* __restrict__ f, int D, int which)
{
    uint2* __restrict__ s16 = reinterpret_cast<uint2*>(which ? G_SV16 : G_SA16);
    uint2* __restrict__ f16 = reinterpret_cast<uint2*>(which ? G_FV16 : G_FA16);
    const float4* __restrict__ fv = reinterpret_cast<const float4*>(f);
    const int D4 = D >> 2;
    const long total = (long)NR * D4;
    const float inv3 = 1.0f / 3.0f;
    for (long i = (long)blockIdx.x*blockDim.x + threadIdx.x; i < total;
         i += (long)gridDim.x*blockDim.x) {
        long row = i / D4;
        int s = (int)(row % NS);
        float4 c = fv[i];
        float4 r;
        if (s == 0) {
            float4 n = fv[i + D4];
            r.x=(c.x+n.x)*0.5f; r.y=(c.y+n.y)*0.5f;
            r.z=(c.z+n.z)*0.5f; r.w=(c.w+n.w)*0.5f;
        } else if (s == NS-1) {
            float4 p = fv[i - D4];
            r.x=(c.x+p.x)*0.5f; r.y=(c.y+p.y)*0.5f;
            r.z=(c.z+p.z)*0.5f; r.w=(c.w+p.w)*0.5f;
        } else {
            float4 p = fv[i - D4];
            float4 n = fv[i + D4];
            r.x=(p.x+c.x+n.x)*inv3; r.y=(p.y+c.y+n.y)*inv3;
            r.z=(p.z+c.z+n.z)*inv3; r.w=(p.w+c.w+n.w)*inv3;
        }
        s16[i] = cvt4(r);
        f16[i] = cvt4(c);
    }
}

// ---------------------------------------------------------------------------
// R1-VALIDATED: M = P @ W (fp32), 16x16 tiles. which=0 -> g_Mv, 1 -> g_Ma
// ---------------------------------------------------------------------------
__global__ void proto_proj_kernel(const float* __restrict__ P,
                                  const float* __restrict__ W,
                                  int D, int C, int which)
{
    float* __restrict__ Cout = which ? g_Ma : g_Mv;
    __shared__ float As[16][16];
    __shared__ float Ws[16][17];
    int tx = threadIdx.x, ty = threadIdx.y;
    int row = blockIdx.y*16 + ty;
    int col = blockIdx.x*16 + tx;
    float acc = 0.f;
    for (int d0 = 0; d0 < D; d0 += 16) {
        As[ty][tx] = P[row*D + d0 + tx];
        Ws[ty][tx] = W[(d0+ty)*C + col];
        __syncthreads();
        #pragma unroll
        for (int kk = 0; kk < 16; kk++) acc += As[ty][kk]*Ws[kk][tx];
        __syncthreads();
    }
    Cout[row*C + col] = acc;
}

// ---------------------------------------------------------------------------
// Trivial scalar fp32 -> bf16. which: 0->pV16, 1->pA16, 2->Mv16, 3->Ma16
// ---------------------------------------------------------------------------
__global__ void cvt_scalar_kernel(const float* __restrict__ in, int n, int which)
{
    __nv_bfloat16* dst = (which == 0) ? G_PV16 : (which == 1) ? G_PA16
                       : (which == 2) ? G_MV16 : G_MA16;
    for (int i = blockIdx.x*blockDim.x + threadIdx.x; i < n; i += gridDim.x*blockDim.x) {
        float v = (which < 2) ? in[i] : (which == 2 ? g_Mv[i] : g_Ma[i]);
        dst[i] = __float2bfloat16(v);
    }
}

// ---------------------------------------------------------------------------
// Fused HMMA energy kernel. gridDim = (NK/BN, NR/BM, 2 modalities).
// 512 threads, 16 warps (4x4), 32x32 warp tiles, 3-stage cp.async pipeline.
// NO register cap (launch_bounds(512) only) -> no spills, occ 1, 16 warps/SM.
// ---------------------------------------------------------------------------
extern __shared__ char dsm[];

__global__ __launch_bounds__(NTH)
void fused_energy_kernel()
{
    __shared__ float red_s[16];

    const int tid = threadIdx.x;
    const int wid = tid >> 5;
    const int lane = tid & 31;
    const int z = blockIdx.z;
    const long row0 = (long)blockIdx.y * BM;
    const long col0 = (long)blockIdx.x * BN;

    const __nv_bfloat16 *A1, *B1, *A2, *B2;
    int D1, D2;
    if (z == 0) { A1 = G_FV16; B1 = G_PV16; D1 = DV; A2 = G_SA16; B2 = G_MV16; D2 = DA; }
    else        { A1 = G_FA16; B1 = G_PA16; D1 = DA; A2 = G_SV16; B2 = G_MA16; D2 = DV; }
    const int n1 = D1 / BK;
    const int nch = n1 + D2 / BK;

    const uint32_t base0 = smem_u32(dsm);

    // A tile: 128 rows x 32 bf16 (64B) per chunk = 512 x 16B units; 1/thread
    auto load_chunk = [&](int c, int stage) {
        const __nv_bfloat16 *A, *B; int D, k0;
        if (c < n1) { A = A1; B = B1; D = D1; k0 = c * BK; }
        else        { A = A2; B = B2; D = D2; k0 = (c - n1) * BK; }
        uint32_t base = base0 + stage * STGB;
        int row = tid >> 2, seg = tid & 3;
        uint32_t d = base + (uint32_t)(row * 80 + seg * 16);
        cp16(d,         A + (row0 + row) * D + k0 + seg * 8);
        cp16(d + ATILE, B + (col0 + row) * D + k0 + seg * 8);
        cp_commit();
    };

    const int wm = (wid >> 2) * 32;   // warp row base (0,32,64,96)
    const int wn = (wid & 3) * 32;    // warp col base
    const int arow = wm + (lane & 7) + ((lane >> 3) & 1) * 8;
    const int acol = (lane >> 4) * 16;           // byte offset (k-half)
    const int l2 = lane & 15;
    const int brow = wn + (l2 & 7);
    const int bcol = ((l2 >> 3) & 1) * 16;

    auto compute_chunk = [&](int stage, float (*acc)[4][4]) {
        uint32_t sA = base0 + stage * STGB;
        uint32_t sB = sA + ATILE;
        #pragma unroll
        for (int ks = 0; ks < 2; ks++) {
            uint32_t a[2][4];
            #pragma unroll
            for (int i = 0; i < 2; i++)
                ldsm4(a[i], sA + (uint32_t)((arow + i * 16) * 80 + acol + ks * 32));
            uint32_t b[4][2];
            #pragma unroll
            for (int j = 0; j < 4; j++)
                ldsm2(b[j], sB + (uint32_t)((brow + j * 8) * 80 + bcol + ks * 32));
            #pragma unroll
            for (int i = 0; i < 2; i++)
                #pragma unroll
                for (int j = 0; j < 4; j++)
                    mma16816(acc[i][j], a[i], b[j]);
        }
    };

    float acc1[2][4][4] = {};
    float acc2[2][4][4] = {};

    load_chunk(0, 0);
    load_chunk(1, 1);

    for (int c = 0; c < nch; c++) {
        if (c + 1 < nch) asm volatile("cp.async.wait_group 1;" ::: "memory");
        else             asm volatile("cp.async.wait_group 0;" ::: "memory");
        __syncthreads();   // chunk c visible; all warps done reading chunk c-1
        if (c + 2 < nch) load_chunk(c + 2, (c + 2) % NSTAGE);
        compute_chunk(c % NSTAGE, (c < n1) ? acc1 : acc2);
    }

    // Epilogue: elementwise softplus on matching fragments, then reduce.
    float local = 0.f;
    #pragma unroll
    for (int i = 0; i < 2; i++)
        #pragma unroll
        for (int j = 0; j < 4; j++)
            #pragma unroll
            for (int r = 0; r < 4; r++) {
                float c1 = acc1[i][j][r];
                float c2 = acc2[i][j][r];
                float sal = LAM * c2 * c2 + (1.0f - LAM) * c1 * c1;
                float x = sal * c1;
                local += fmaxf(x, 0.f) + log1pf(__expf(-fabsf(x)));
            }
    #pragma unroll
    for (int o = 16; o > 0; o >>= 1)
        local += __shfl_xor_sync(0xFFFFFFFF, local, o);
    if (lane == 0) red_s[wid] = local;
    __syncthreads();
    if (tid == 0) {
        float s = 0.f;
        #pragma unroll
        for (int w = 0; w < 16; w++) s += red_s[w];
        g_partials[(z * gridDim.y + blockIdx.y) * gridDim.x + blockIdx.x] = s;
    }
}

// ---------------------------------------------------------------------------
// Deterministic final reduction
// ---------------------------------------------------------------------------
__global__ void final_reduce_kernel(float* __restrict__ out)
{
    __shared__ double red[256];
    double s = 0.0;
    for (int i = threadIdx.x; i < NBLOCKS; i += 256) s += (double)g_partials[i];
    red[threadIdx.x] = s;
    __syncthreads();
    for (int st = 128; st > 0; st >>= 1) {
        if (threadIdx.x < st) red[threadIdx.x] += red[threadIdx.x + st];
        __syncthreads();
    }
    if (threadIdx.x == 0) out[0] = (float)(-red[0]);
}

// ---------------------------------------------------------------------------
extern "C" void kernel_launch(void* const* d_in, const int* in_sizes, int n_in,
                              void* d_out, int out_size)
{
    const float* fv  = (const float*)d_in[0];   // (8,2048,768)
    const float* fa  = (const float*)d_in[1];   // (8,2048,512)
    const float* pv  = (const float*)d_in[2];   // (512,768)
    const float* pa  = (const float*)d_in[3];   // (512,512)
    const float* wav = (const float*)d_in[4];   // (768,512)
    const float* wva = (const float*)d_in[5];   // (512,768)
    float* out = (float*)d_out;

    cudaFuncSetAttribute(fused_energy_kernel,
                         cudaFuncAttributeMaxDynamicSharedMemorySize, FUSED_SMEM);

    smooth_cvt2_kernel<<<4096, 256>>>(fv, DV, 1);   // bf16 smooth + feat (vision)
    smooth_cvt2_kernel<<<4096, 256>>>(fa, DA, 0);   // bf16 smooth + feat (audio)

    // Validated fp32 M production + scalar bf16 conversion
    proto_proj_kernel<<<dim3(DA/16, NK/16), dim3(16,16)>>>(pv, wav, DV, DA, 0);  // g_Mv
    proto_proj_kernel<<<dim3(DV/16, NK/16), dim3(16,16)>>>(pa, wva, DA, DV, 1);  // g_Ma

    cvt_scalar_kernel<<<512, 256>>>(pv, NK*DV, 0);
    cvt_scalar_kernel<<<512, 256>>>(pa, NK*DA, 1);
    cvt_scalar_kernel<<<512, 256>>>(nullptr, NK*DA, 2);
    cvt_scalar_kernel<<<512, 256>>>(nullptr, NK*DV, 3);

    fused_energy_kernel<<<dim3(NK/BN, NR/BM, 2), NTH, FUSED_SMEM>>>();

    final_reduce_kernel<<<1, 256>>>(out);
}

// round 9
// speedup vs baseline: 1.0194x; 1.0194x over previous
#include <cuda_runtime.h>
#include <cuda_bf16.h>
#include <math.h>
#include <stdint.h>

// Problem dims (fixed by setup_inputs)
#define NB 8
#define NS 2048
#define DV 768
#define DA 512
#define NK 512
#define NR (NB*NS)            // 16384 rows
#define LAM 0.3f

// Fused GEMM tiling (mma.sync m16n8k16 bf16) -- R6-validated core geometry
#define BM 128
#define BN 128
#define BK 32                 // bf16 k per chunk
#define NTH 256               // 8 warps, 2x4 grid, 64x32 warp tiles
#define ATILE 10240           // 128 rows * 80 B
#define STGB 20480            // one stage: A tile + B tile
#define NSTAGE 6              // paired-chunk pipeline, pair prefetch distance 2
#define FUSED_SMEM (NSTAGE*STGB)   // 122880
#define NBLOCKS ((NK/BN)*(NR/BM)*2)   // 1024

// ---------------- device scratch; bf16 stored in uint4 arrays (16B-aligned) --
__device__ uint4 g_fV16u[(size_t)NR*DV/8];   // bf16 feat_vision
__device__ uint4 g_fA16u[(size_t)NR*DA/8];
__device__ uint4 g_sV16u[(size_t)NR*DV/8];   // bf16 smooth(feat_vision)
__device__ uint4 g_sA16u[(size_t)NR*DA/8];
__device__ uint4 g_pV16u[NK*DV/8];           // bf16 proto_vision
__device__ uint4 g_pA16u[NK*DA/8];
__device__ uint4 g_Mv16u[NK*DA/8];           // bf16 proto_v @ W_a2v
__device__ uint4 g_Ma16u[NK*DV/8];
__device__ float g_Mv[NK*DA];                // fp32 M (validated producer)
__device__ float g_Ma[NK*DV];
__device__ float g_partials[NBLOCKS];

#define G_FV16 ((__nv_bfloat16*)g_fV16u)
#define G_FA16 ((__nv_bfloat16*)g_fA16u)
#define G_SV16 ((__nv_bfloat16*)g_sV16u)
#define G_SA16 ((__nv_bfloat16*)g_sA16u)
#define G_PV16 ((__nv_bfloat16*)g_pV16u)
#define G_PA16 ((__nv_bfloat16*)g_pA16u)
#define G_MV16 ((__nv_bfloat16*)g_Mv16u)
#define G_MA16 ((__nv_bfloat16*)g_Ma16u)

// ---------------- helpers ----------------
__device__ __forceinline__ uint32_t smem_u32(const void* p) {
    uint32_t a;
    asm("{ .reg .u64 t; cvta.to.shared.u64 t, %1; cvt.u32.u64 %0, t; }" : "=r"(a) : "l"(p));
    return a;
}
__device__ __forceinline__ void cp16(uint32_t dst, const void* src) {
    asm volatile("cp.async.cg.shared.global [%0], [%1], 16;" :: "r"(dst), "l"(src) : "memory");
}
__device__ __forceinline__ void cp_commit() {
    asm volatile("cp.async.commit_group;" ::: "memory");
}
__device__ __forceinline__ void ldsm4(uint32_t* r, uint32_t addr) {
    asm volatile("ldmatrix.sync.aligned.m8n8.x4.shared.b16 {%0,%1,%2,%3}, [%4];"
                 : "=r"(r[0]), "=r"(r[1]), "=r"(r[2]), "=r"(r[3]) : "r"(addr));
}
__device__ __forceinline__ void ldsm2(uint32_t* r, uint32_t addr) {
    asm volatile("ldmatrix.sync.aligned.m8n8.x2.shared.b16 {%0,%1}, [%2];"
                 : "=r"(r[0]), "=r"(r[1]) : "r"(addr));
}
__device__ __forceinline__ void mma16816(float* c, const uint32_t* a, const uint32_t* b) {
    asm volatile(
        "mma.sync.aligned.m16n8k16.row.col.f32.bf16.bf16.f32 "
        "{%0,%1,%2,%3}, {%4,%5,%6,%7}, {%8,%9}, {%0,%1,%2,%3};"
        : "+f"(c[0]), "+f"(c[1]), "+f"(c[2]), "+f"(c[3])
        : "r"(a[0]), "r"(a[1]), "r"(a[2]), "r"(a[3]), "r"(b[0]), "r"(b[1]));
}
__device__ __forceinline__ uint2 cvt4(float4 v) {
    __nv_bfloat162 lo = __floats2bfloat162_rn(v.x, v.y);
    __nv_bfloat162 hi = __floats2bfloat162_rn(v.z, v.w);
    uint2 r;
    r.x = *reinterpret_cast<uint32_t*>(&lo);
    r.y = *reinterpret_cast<uint32_t*>(&hi);
    return r;
}

// ---------------------------------------------------------------------------
// R1-VALIDATED smooth computation + bf16 dual store (smooth + feat).
// ---------------------------------------------------------------------------
__global__ void smooth_cvt2_kernel(const float* __restrict__ f, int D, int which)
{
    uint2* __restrict__ s16 = reinterpret_cast<uint2*>(which ? G_SV16 : G_SA16);
    uint2* __restrict__ f16 = reinterpret_cast<uint2*>(which ? G_FV16 : G_FA16);
    const float4* __restrict__ fv = reinterpret_cast<const float4*>(f);
    const int D4 = D >> 2;
    const long total = (long)NR * D4;
    const float inv3 = 1.0f / 3.0f;
    for (long i = (long)blockIdx.x*blockDim.x + threadIdx.x; i < total;
         i += (long)gridDim.x*blockDim.x) {
        long row = i / D4;
        int s = (int)(row % NS);
        float4 c = fv[i];
        float4 r;
        if (s == 0) {
            float4 n = fv[i + D4];
            r.x=(c.x+n.x)*0.5f; r.y=(c.y+n.y)*0.5f;
            r.z=(c.z+n.z)*0.5f; r.w=(c.w+n.w)*0.5f;
        } else if (s == NS-1) {
            float4 p = fv[i - D4];
            r.x=(c.x+p.x)*0.5f; r.y=(c.y+p.y)*0.5f;
            r.z=(c.z+p.z)*0.5f; r.w=(c.w+p.w)*0.5f;
        } else {
            float4 p = fv[i - D4];
            float4 n = fv[i + D4];
            r.x=(p.x+c.x+n.x)*inv3; r.y=(p.y+c.y+n.y)*inv3;
            r.z=(p.z+c.z+n.z)*inv3; r.w=(p.w+c.w+n.w)*inv3;
        }
        s16[i] = cvt4(r);
        f16[i] = cvt4(c);
    }
}

// ---------------------------------------------------------------------------
// R1-VALIDATED: M = P @ W (fp32), 16x16 tiles. which=0 -> g_Mv, 1 -> g_Ma
// ---------------------------------------------------------------------------
__global__ void proto_proj_kernel(const float* __restrict__ P,
                                  const float* __restrict__ W,
                                  int D, int C, int which)
{
    float* __restrict__ Cout = which ? g_Ma : g_Mv;
    __shared__ float As[16][16];
    __shared__ float Ws[16][17];
    int tx = threadIdx.x, ty = threadIdx.y;
    int row = blockIdx.y*16 + ty;
    int col = blockIdx.x*16 + tx;
    float acc = 0.f;
    for (int d0 = 0; d0 < D; d0 += 16) {
        As[ty][tx] = P[row*D + d0 + tx];
        Ws[ty][tx] = W[(d0+ty)*C + col];
        __syncthreads();
        #pragma unroll
        for (int kk = 0; kk < 16; kk++) acc += As[ty][kk]*Ws[kk][tx];
        __syncthreads();
    }
    Cout[row*C + col] = acc;
}

// ---------------------------------------------------------------------------
// All fp32->bf16 conversions in ONE launch (keeps fused kernel at index 5 for ncu).
// Segments: pV (NK*DV), pA (NK*DA), Mv (NK*DA), Ma (NK*DV).
// ---------------------------------------------------------------------------
__global__ void cvt_all_kernel(const float* __restrict__ pv, const float* __restrict__ pa)
{
    const int nPV = NK*DV, nPA = NK*DA, nMV = NK*DA, nMA = NK*DV;
    const int total = nPV + nPA + nMV + nMA;
    for (int i = blockIdx.x*blockDim.x + threadIdx.x; i < total; i += gridDim.x*blockDim.x) {
        if (i < nPV)                      G_PV16[i] = __float2bfloat16(pv[i]);
        else if (i < nPV+nPA)             G_PA16[i-nPV] = __float2bfloat16(pa[i-nPV]);
        else if (i < nPV+nPA+nMV)         G_MV16[i-nPV-nPA] = __float2bfloat16(g_Mv[i-nPV-nPA]);
        else                              G_MA16[i-nPV-nPA-nMV] = __float2bfloat16(g_Ma[i-nPV-nPA-nMV]);
    }
}

// ---------------------------------------------------------------------------
// Fused HMMA energy kernel. gridDim = (NK/BN, NR/BM, 2 modalities).
// R6-validated 256-thread core (2x4 warps, 64x32 tiles). Paired-chunk
// 6-stage cp.async pipeline: one barrier + one commit-group per 2 chunks.
// ---------------------------------------------------------------------------
extern __shared__ char dsm[];

__global__ __launch_bounds__(NTH)
void fused_energy_kernel()
{
    __shared__ float red_s[8];

    const int tid = threadIdx.x;
    const int wid = tid >> 5;
    const int lane = tid & 31;
    const int z = blockIdx.z;
    const long row0 = (long)blockIdx.y * BM;
    const long col0 = (long)blockIdx.x * BN;

    const __nv_bfloat16 *A1, *B1, *A2, *B2;
    int D1, D2;
    if (z == 0) { A1 = G_FV16; B1 = G_PV16; D1 = DV; A2 = G_SA16; B2 = G_MV16; D2 = DA; }
    else        { A1 = G_FA16; B1 = G_PA16; D1 = DA; A2 = G_SV16; B2 = G_MA16; D2 = DV; }
    const int n1 = D1 / BK;
    const int nch = n1 + D2 / BK;   // 40, n1 even in both modalities

    const uint32_t base0 = smem_u32(dsm);

    // one chunk -> one stage (A: 512x16B units, B: 512x16B; 2+2 per thread)
    auto load_chunk = [&](int c, int stage) {
        const __nv_bfloat16 *A, *B; int D, k0;
        if (c < n1) { A = A1; B = B1; D = D1; k0 = c * BK; }
        else        { A = A2; B = B2; D = D2; k0 = (c - n1) * BK; }
        uint32_t base = base0 + stage * STGB;
        #pragma unroll
        for (int r = 0; r < 2; r++) {
            int u = tid + r * 256;
            int row = u >> 2, seg = u & 3;
            uint32_t d = base + (uint32_t)(row * 80 + seg * 16);
            cp16(d,         A + (row0 + row) * D + k0 + seg * 8);
            cp16(d + ATILE, B + (col0 + row) * D + k0 + seg * 8);
        }
    };
    // pair loader: chunks c, c+1 -> stages c%NSTAGE, (c+1)%NSTAGE; ONE group
    auto load_pair = [&](int c) {
        load_chunk(c, c % NSTAGE);
        if (c + 1 < nch) load_chunk(c + 1, (c + 1) % NSTAGE);
        cp_commit();
    };

    const int wm = (wid >> 2) * 64;   // warp row base
    const int wn = (wid & 3) * 32;    // warp col base
    const int arow = wm + (lane & 7) + ((lane >> 3) & 1) * 8;
    const int acol = (lane >> 4) * 16;           // byte offset (k-half)
    const int l2 = lane & 15;
    const int brow = wn + (l2 & 7);
    const int bcol = ((l2 >> 3) & 1) * 16;

    auto compute_chunk = [&](int stage, float (*acc)[4][4]) {
        uint32_t sA = base0 + stage * STGB;
        uint32_t sB = sA + ATILE;
        #pragma unroll
        for (int ks = 0; ks < 2; ks++) {
            uint32_t a[4][4];
            #pragma unroll
            for (int i = 0; i < 4; i++)
                ldsm4(a[i], sA + (uint32_t)((arow + i * 16) * 80 + acol + ks * 32));
            uint32_t b[4][2];
            #pragma unroll
            for (int j = 0; j < 4; j++)
                ldsm2(b[j], sB + (uint32_t)((brow + j * 8) * 80 + bcol + ks * 32));
            #pragma unroll
            for (int i = 0; i < 4; i++)
                #pragma unroll
                for (int j = 0; j < 4; j++)
                    mma16816(acc[i][j], a[i], b[j]);
        }
    };

    float acc1[4][4][4] = {};
    float acc2[4][4][4] = {};

    load_pair(0);   // chunks 0,1   (group 0)
    load_pair(2);   // chunks 2,3   (group 1)

    for (int c = 0; c < nch; c += 2) {
        // allow newest group outstanding -> pair c fully landed
        asm volatile("cp.async.wait_group 1;" ::: "memory");
        __syncthreads();   // pair c visible; all warps done with pair c-2 stages
        if (c + 4 < nch) load_pair(c + 4);   // stages of pair c-2 (finished pre-sync)
        compute_chunk(c % NSTAGE, (c < n1) ? acc1 : acc2);
        if (c + 1 < nch)
            compute_chunk((c + 1) % NSTAGE, ((c + 1) < n1) ? acc1 : acc2);
    }

    // Epilogue: elementwise softplus on matching fragments, then reduce.
    float local = 0.f;
    #pragma unroll
    for (int i = 0; i < 4; i++)
        #pragma unroll
        for (int j = 0; j < 4; j++)
            #pragma unroll
            for (int r = 0; r < 4; r++) {
                float c1 = acc1[i][j][r];
                float c2 = acc2[i][j][r];
                float sal = LAM * c2 * c2 + (1.0f - LAM) * c1 * c1;
                float x = sal * c1;
                local += fmaxf(x, 0.f) + log1pf(__expf(-fabsf(x)));
            }
    #pragma unroll
    for (int o = 16; o > 0; o >>= 1)
        local += __shfl_xor_sync(0xFFFFFFFF, local, o);
    if (lane == 0) red_s[wid] = local;
    __syncthreads();
    if (tid == 0) {
        float s = 0.f;
        #pragma unroll
        for (int w = 0; w < 8; w++) s += red_s[w];
        g_partials[(z * gridDim.y + blockIdx.y) * gridDim.x + blockIdx.x] = s;
    }
}

// ---------------------------------------------------------------------------
// Deterministic final reduction
// ---------------------------------------------------------------------------
__global__ void final_reduce_kernel(float* __restrict__ out)
{
    __shared__ double red[256];
    double s = 0.0;
    for (int i = threadIdx.x; i < NBLOCKS; i += 256) s += (double)g_partials[i];
    red[threadIdx.x] = s;
    __syncthreads();
    for (int st = 128; st > 0; st >>= 1) {
        if (threadIdx.x < st) red[threadIdx.x] += red[threadIdx.x + st];
        __syncthreads();
    }
    if (threadIdx.x == 0) out[0] = (float)(-red[0]);
}

// ---------------------------------------------------------------------------
extern "C" void kernel_launch(void* const* d_in, const int* in_sizes, int n_in,
                              void* d_out, int out_size)
{
    const float* fv  = (const float*)d_in[0];   // (8,2048,768)
    const float* fa  = (const float*)d_in[1];   // (8,2048,512)
    const float* pv  = (const float*)d_in[2];   // (512,768)
    const float* pa  = (const float*)d_in[3];   // (512,512)
    const float* wav = (const float*)d_in[4];   // (768,512)
    const float* wva = (const float*)d_in[5];   // (512,768)
    float* out = (float*)d_out;

    cudaFuncSetAttribute(fused_energy_kernel,
                         cudaFuncAttributeMaxDynamicSharedMemorySize, FUSED_SMEM);

    // launch indices 0..4 (fused at 5 -> captured by ncu -s 5 -c 1)
    smooth_cvt2_kernel<<<4096, 256>>>(fv, DV, 1);                                // 0
    smooth_cvt2_kernel<<<4096, 256>>>(fa, DA, 0);                                // 1
    proto_proj_kernel<<<dim3(DA/16, NK/16), dim3(16,16)>>>(pv, wav, DV, DA, 0);  // 2
    proto_proj_kernel<<<dim3(DV/16, NK/16), dim3(16,16)>>>(pa, wva, DA, DV, 1);  // 3
    cvt_all_kernel<<<1024, 256>>>(pv, pa);                                       // 4

    fused_energy_kernel<<<dim3(NK/BN, NR/BM, 2), NTH, FUSED_SMEM>>>();           // 5

    final_reduce_kernel<<<1, 256>>>(out);                                        // 6
}

// round 11
// speedup vs baseline: 1.0629x; 1.0426x over previous
#include <cuda_runtime.h>
#include <cuda_bf16.h>
#include <math.h>
#include <stdint.h>

// Problem dims (fixed by setup_inputs)
#define NB 8
#define NS 2048
#define DV 768
#define DA 512
#define NK 512
#define NR (NB*NS)            // 16384 rows
#define LAM 0.3f

// Fused GEMM tiling (mma.sync m16n8k16 bf16) -- R6/R9-validated core
#define BM 128
#define BN 128
#define BK 32                 // bf16 k per chunk
#define NTH 256               // 8 warps, 2x4 grid, 64x32 warp tiles
#define ATILE 10240           // 128 rows * 80 B
#define STGB 20480            // one stage: A tile + B tile
#define NSTAGE 6              // paired-chunk pipeline
#define FUSED_SMEM (NSTAGE*STGB)   // 122880
#define NBLOCKS ((NK/BN)*(NR/BM)*2)   // 1024

// ---------------- device scratch; bf16 stored in uint4 arrays (16B-aligned) --
__device__ uint4 g_fV16u[(size_t)NR*DV/8];   // bf16 feat_vision
__device__ uint4 g_fA16u[(size_t)NR*DA/8];
__device__ uint4 g_sV16u[(size_t)NR*DV/8];   // bf16 smooth(feat_vision)
__device__ uint4 g_sA16u[(size_t)NR*DA/8];
__device__ uint4 g_pV16u[NK*DV/8];           // bf16 proto_vision
__device__ uint4 g_pA16u[NK*DA/8];
__device__ uint4 g_Mv16u[NK*DA/8];           // bf16 proto_v @ W_a2v
__device__ uint4 g_Ma16u[NK*DV/8];
__device__ float g_Mv[NK*DA];                // fp32 M (validated producer)
__device__ float g_Ma[NK*DV];
__device__ float g_partials[NBLOCKS];

#define G_FV16 ((__nv_bfloat16*)g_fV16u)
#define G_FA16 ((__nv_bfloat16*)g_fA16u)
#define G_SV16 ((__nv_bfloat16*)g_sV16u)
#define G_SA16 ((__nv_bfloat16*)g_sA16u)
#define G_PV16 ((__nv_bfloat16*)g_pV16u)
#define G_PA16 ((__nv_bfloat16*)g_pA16u)
#define G_MV16 ((__nv_bfloat16*)g_Mv16u)
#define G_MA16 ((__nv_bfloat16*)g_Ma16u)

// ---------------- helpers ----------------
__device__ __forceinline__ uint32_t smem_u32(const void* p) {
    uint32_t a;
    asm("{ .reg .u64 t; cvta.to.shared.u64 t, %1; cvt.u32.u64 %0, t; }" : "=r"(a) : "l"(p));
    return a;
}
__device__ __forceinline__ void cp16(uint32_t dst, const void* src) {
    asm volatile("cp.async.cg.shared.global [%0], [%1], 16;" :: "r"(dst), "l"(src) : "memory");
}
__device__ __forceinline__ void cp_commit() {
    asm volatile("cp.async.commit_group;" ::: "memory");
}
__device__ __forceinline__ void ldsm4(uint32_t* r, uint32_t addr) {
    asm volatile("ldmatrix.sync.aligned.m8n8.x4.shared.b16 {%0,%1,%2,%3}, [%4];"
                 : "=r"(r[0]), "=r"(r[1]), "=r"(r[2]), "=r"(r[3]) : "r"(addr));
}
__device__ __forceinline__ void ldsm2(uint32_t* r, uint32_t addr) {
    asm volatile("ldmatrix.sync.aligned.m8n8.x2.shared.b16 {%0,%1}, [%2];"
                 : "=r"(r[0]), "=r"(r[1]) : "r"(addr));
}
__device__ __forceinline__ void mma16816(float* c, const uint32_t* a, const uint32_t* b) {
    asm volatile(
        "mma.sync.aligned.m16n8k16.row.col.f32.bf16.bf16.f32 "
        "{%0,%1,%2,%3}, {%4,%5,%6,%7}, {%8,%9}, {%0,%1,%2,%3};"
        : "+f"(c[0]), "+f"(c[1]), "+f"(c[2]), "+f"(c[3])
        : "r"(a[0]), "r"(a[1]), "r"(a[2]), "r"(a[3]), "r"(b[0]), "r"(b[1]));
}
__device__ __forceinline__ uint2 cvt4(float4 v) {
    __nv_bfloat162 lo = __floats2bfloat162_rn(v.x, v.y);
    __nv_bfloat162 hi = __floats2bfloat162_rn(v.z, v.w);
    uint2 r;
    r.x = *reinterpret_cast<uint32_t*>(&lo);
    r.y = *reinterpret_cast<uint32_t*>(&hi);
    return r;
}

// ---------------------------------------------------------------------------
// Both smooth+cvt passes in ONE launch (blockIdx.z selects modality).
// Body identical to validated smooth_cvt2.
// ---------------------------------------------------------------------------
__global__ void smooth_all_kernel(const float* __restrict__ fvin,
                                  const float* __restrict__ fain)
{
    const int vz = (blockIdx.z == 0);            // z=0: vision, z=1: audio
    const float* f = vz ? fvin : fain;
    const int D = vz ? DV : DA;
    uint2* __restrict__ s16 = reinterpret_cast<uint2*>(vz ? G_SV16 : G_SA16);
    uint2* __restrict__ f16 = reinterpret_cast<uint2*>(vz ? G_FV16 : G_FA16);
    const float4* __restrict__ fv = reinterpret_cast<const float4*>(f);
    const int D4 = D >> 2;
    const long total = (long)NR * D4;
    const float inv3 = 1.0f / 3.0f;
    for (long i = (long)blockIdx.x*blockDim.x + threadIdx.x; i < total;
         i += (long)gridDim.x*blockDim.x) {
        long row = i / D4;
        int s = (int)(row % NS);
        float4 c = fv[i];
        float4 r;
        if (s == 0) {
            float4 n = fv[i + D4];
            r.x=(c.x+n.x)*0.5f; r.y=(c.y+n.y)*0.5f;
            r.z=(c.z+n.z)*0.5f; r.w=(c.w+n.w)*0.5f;
        } else if (s == NS-1) {
            float4 p = fv[i - D4];
            r.x=(c.x+p.x)*0.5f; r.y=(c.y+p.y)*0.5f;
            r.z=(c.z+p.z)*0.5f; r.w=(c.w+p.w)*0.5f;
        } else {
            float4 p = fv[i - D4];
            float4 n = fv[i + D4];
            r.x=(p.x+c.x+n.x)*inv3; r.y=(p.y+c.y+n.y)*inv3;
            r.z=(p.z+c.z+n.z)*inv3; r.w=(p.w+c.w+n.w)*inv3;
        }
        s16[i] = cvt4(r);
        f16[i] = cvt4(c);
    }
}

// ---------------------------------------------------------------------------
// Both M = P @ W GEMMs in ONE launch (blockIdx.z selects which).
// Inner code byte-identical to R1-validated proto_proj.
// z=0: Mv (P=pv, W=wav, D=DV, C=DA; needs blockIdx.x < DA/16=32)
// z=1: Ma (P=pa, W=wva, D=DA, C=DV; all 48 x-blocks)
// ---------------------------------------------------------------------------
__global__ void proto_all_kernel(const float* __restrict__ pv,
                                 const float* __restrict__ pa,
                                 const float* __restrict__ wav,
                                 const float* __restrict__ wva)
{
    const int za = (blockIdx.z != 0);
    if (!za && blockIdx.x >= DA/16) return;      // uniform per block, pre-sync
    const float* __restrict__ P = za ? pa : pv;
    const float* __restrict__ W = za ? wva : wav;
    const int D = za ? DA : DV;
    const int C = za ? DV : DA;
    float* __restrict__ Cout = za ? g_Ma : g_Mv;

    __shared__ float As[16][16];
    __shared__ float Ws[16][17];
    int tx = threadIdx.x, ty = threadIdx.y;
    int row = blockIdx.y*16 + ty;
    int col = blockIdx.x*16 + tx;
    float acc = 0.f;
    for (int d0 = 0; d0 < D; d0 += 16) {
        As[ty][tx] = P[row*D + d0 + tx];
        Ws[ty][tx] = W[(d0+ty)*C + col];
        __syncthreads();
        #pragma unroll
        for (int kk = 0; kk < 16; kk++) acc += As[ty][kk]*Ws[kk][tx];
        __syncthreads();
    }
    Cout[row*C + col] = acc;
}

// ---------------------------------------------------------------------------
// All fp32->bf16 conversions in ONE launch (R9-validated).
// Segments: pV (NK*DV), pA (NK*DA), Mv (NK*DA), Ma (NK*DV).
// ---------------------------------------------------------------------------
__global__ void cvt_all_kernel(const float* __restrict__ pv, const float* __restrict__ pa)
{
    const int nPV = NK*DV, nPA = NK*DA, nMV = NK*DA, nMA = NK*DV;
    const int total = nPV + nPA + nMV + nMA;
    for (int i = blockIdx.x*blockDim.x + threadIdx.x; i < total; i += gridDim.x*blockDim.x) {
        if (i < nPV)                      G_PV16[i] = __float2bfloat16(pv[i]);
        else if (i < nPV+nPA)             G_PA16[i-nPV] = __float2bfloat16(pa[i-nPV]);
        else if (i < nPV+nPA+nMV)         G_MV16[i-nPV-nPA] = __float2bfloat16(g_Mv[i-nPV-nPA]);
        else                              G_MA16[i-nPV-nPA-nMV] = __float2bfloat16(g_Ma[i-nPV-nPA-nMV]);
    }
}

// ---------------------------------------------------------------------------
// Fused HMMA energy kernel (R9-validated, unchanged).
// gridDim = (NK/BN, NR/BM, 2). Paired-chunk 6-stage cp.async pipeline.
// ---------------------------------------------------------------------------
extern __shared__ char dsm[];

__global__ __launch_bounds__(NTH)
void fused_energy_kernel()
{
    __shared__ float red_s[8];

    const int tid = threadIdx.x;
    const int wid = tid >> 5;
    const int lane = tid & 31;
    const int z = blockIdx.z;
    const long row0 = (long)blockIdx.y * BM;
    const long col0 = (long)blockIdx.x * BN;

    const __nv_bfloat16 *A1, *B1, *A2, *B2;
    int D1, D2;
    if (z == 0) { A1 = G_FV16; B1 = G_PV16; D1 = DV; A2 = G_SA16; B2 = G_MV16; D2 = DA; }
    else        { A1 = G_FA16; B1 = G_PA16; D1 = DA; A2 = G_SV16; B2 = G_MA16; D2 = DV; }
    const int n1 = D1 / BK;
    const int nch = n1 + D2 / BK;   // 40, n1 even in both modalities

    const uint32_t base0 = smem_u32(dsm);

    auto load_chunk = [&](int c, int stage) {
        const __nv_bfloat16 *A, *B; int D, k0;
        if (c < n1) { A = A1; B = B1; D = D1; k0 = c * BK; }
        else        { A = A2; B = B2; D = D2; k0 = (c - n1) * BK; }
        uint32_t base = base0 + stage * STGB;
        #pragma unroll
        for (int r = 0; r < 2; r++) {
            int u = tid + r * 256;
            int row = u >> 2, seg = u & 3;
            uint32_t d = base + (uint32_t)(row * 80 + seg * 16);
            cp16(d,         A + (row0 + row) * D + k0 + seg * 8);
            cp16(d + ATILE, B + (col0 + row) * D + k0 + seg * 8);
        }
    };
    auto load_pair = [&](int c) {
        load_chunk(c, c % NSTAGE);
        if (c + 1 < nch) load_chunk(c + 1, (c + 1) % NSTAGE);
        cp_commit();
    };

    const int wm = (wid >> 2) * 64;   // warp row base
    const int wn = (wid & 3) * 32;    // warp col base
    const int arow = wm + (lane & 7) + ((lane >> 3) & 1) * 8;
    const int acol = (lane >> 4) * 16;           // byte offset (k-half)
    const int l2 = lane & 15;
    const int brow = wn + (l2 & 7);
    const int bcol = ((l2 >> 3) & 1) * 16;

    auto compute_chunk = [&](int stage, float (*acc)[4][4]) {
        uint32_t sA = base0 + stage * STGB;
        uint32_t sB = sA + ATILE;
        #pragma unroll
        for (int ks = 0; ks < 2; ks++) {
            uint32_t a[4][4];
            #pragma unroll
            for (int i = 0; i < 4; i++)
                ldsm4(a[i], sA + (uint32_t)((arow + i * 16) * 80 + acol + ks * 32));
            uint32_t b[4][2];
            #pragma unroll
            for (int j = 0; j < 4; j++)
                ldsm2(b[j], sB + (uint32_t)((brow + j * 8) * 80 + bcol + ks * 32));
            #pragma unroll
            for (int i = 0; i < 4; i++)
                #pragma unroll
                for (int j = 0; j < 4; j++)
                    mma16816(acc[i][j], a[i], b[j]);
        }
    };

    float acc1[4][4][4] = {};
    float acc2[4][4][4] = {};

    load_pair(0);
    load_pair(2);

    for (int c = 0; c < nch; c += 2) {
        asm volatile("cp.async.wait_group 1;" ::: "memory");
        __syncthreads();
        if (c + 4 < nch) load_pair(c + 4);
        compute_chunk(c % NSTAGE, (c < n1) ? acc1 : acc2);
        if (c + 1 < nch)
            compute_chunk((c + 1) % NSTAGE, ((c + 1) < n1) ? acc1 : acc2);
    }

    float local = 0.f;
    #pragma unroll
    for (int i = 0; i < 4; i++)
        #pragma unroll
        for (int j = 0; j < 4; j++)
            #pragma unroll
            for (int r = 0; r < 4; r++) {
                float c1 = acc1[i][j][r];
                float c2 = acc2[i][j][r];
                float sal = LAM * c2 * c2 + (1.0f - LAM) * c1 * c1;
                float x = sal * c1;
                local += fmaxf(x, 0.f) + log1pf(__expf(-fabsf(x)));
            }
    #pragma unroll
    for (int o = 16; o > 0; o >>= 1)
        local += __shfl_xor_sync(0xFFFFFFFF, local, o);
    if (lane == 0) red_s[wid] = local;
    __syncthreads();
    if (tid == 0) {
        float s = 0.f;
        #pragma unroll
        for (int w = 0; w < 8; w++) s += red_s[w];
        g_partials[(z * gridDim.y + blockIdx.y) * gridDim.x + blockIdx.x] = s;
    }
}

// ---------------------------------------------------------------------------
// Deterministic final reduction
// ---------------------------------------------------------------------------
__global__ void final_reduce_kernel(float* __restrict__ out)
{
    __shared__ double red[256];
    double s = 0.0;
    for (int i = threadIdx.x; i < NBLOCKS; i += 256) s += (double)g_partials[i];
    red[threadIdx.x] = s;
    __syncthreads();
    for (int st = 128; st > 0; st >>= 1) {
        if (threadIdx.x < st) red[threadIdx.x] += red[threadIdx.x + st];
        __syncthreads();
    }
    if (threadIdx.x == 0) out[0] = (float)(-red[0]);
}

// ---------------------------------------------------------------------------
extern "C" void kernel_launch(void* const* d_in, const int* in_sizes, int n_in,
                              void* d_out, int out_size)
{
    const float* fv  = (const float*)d_in[0];   // (8,2048,768)
    const float* fa  = (const float*)d_in[1];   // (8,2048,512)
    const float* pv  = (const float*)d_in[2];   // (512,768)
    const float* pa  = (const float*)d_in[3];   // (512,512)
    const float* wav = (const float*)d_in[4];   // (768,512)
    const float* wva = (const float*)d_in[5];   // (512,768)
    float* out = (float*)d_out;

    cudaFuncSetAttribute(fused_energy_kernel,
                         cudaFuncAttributeMaxDynamicSharedMemorySize, FUSED_SMEM);

    smooth_all_kernel<<<dim3(2048, 1, 2), 256>>>(fv, fa);                         // 0
    proto_all_kernel<<<dim3(DV/16, NK/16, 2), dim3(16,16)>>>(pv, pa, wav, wva);   // 1
    cvt_all_kernel<<<1024, 256>>>(pv, pa);                                        // 2

    fused_energy_kernel<<<dim3(NK/BN, NR/BM, 2), NTH, FUSED_SMEM>>>();            // 3

    final_reduce_kernel<<<1, 256>>>(out);                                         // 4
}

// round 12
// speedup vs baseline: 1.7133x; 1.6119x over previous
#include <cuda_runtime.h>
#include <cuda_bf16.h>
#include <math.h>
#include <stdint.h>

// Problem dims (fixed by setup_inputs)
#define NB 8
#define NS 2048
#define DV 768
#define DA 512
#define NK 512
#define NR (NB*NS)            // 16384 rows
#define LAM 0.3f

// Fused GEMM tiling (mma.sync m16n8k16 bf16)
#define BM 128
#define BN 128
#define BK 32                 // bf16 k per chunk
#define NTH 256               // 8 warps, 2x4 grid, 64x32 warp tiles
#define ATILE 10240           // 128 rows * 80 B
#define STGB 20480            // one stage: A tile + B tile
#define NSTAGE 8              // power of two -> stage = c & 7
#define FUSED_SMEM (NSTAGE*STGB)   // 163840
#define NBLOCKS ((NK/BN)*(NR/BM)*2)   // 1024

// ---------------- device scratch; bf16 stored in uint4 arrays (16B-aligned) --
__device__ uint4 g_fV16u[(size_t)NR*DV/8];   // bf16 feat_vision
__device__ uint4 g_fA16u[(size_t)NR*DA/8];
__device__ uint4 g_sV16u[(size_t)NR*DV/8];   // bf16 smooth(feat_vision)
__device__ uint4 g_sA16u[(size_t)NR*DA/8];
__device__ uint4 g_pV16u[NK*DV/8];           // bf16 proto_vision
__device__ uint4 g_pA16u[NK*DA/8];
__device__ uint4 g_Mv16u[NK*DA/8];           // bf16 proto_v @ W_a2v
__device__ uint4 g_Ma16u[NK*DV/8];
__device__ float g_Mv[NK*DA];                // fp32 M (validated producer)
__device__ float g_Ma[NK*DV];
__device__ float g_partials[NBLOCKS];

#define G_FV16 ((__nv_bfloat16*)g_fV16u)
#define G_FA16 ((__nv_bfloat16*)g_fA16u)
#define G_SV16 ((__nv_bfloat16*)g_sV16u)
#define G_SA16 ((__nv_bfloat16*)g_sA16u)
#define G_PV16 ((__nv_bfloat16*)g_pV16u)
#define G_PA16 ((__nv_bfloat16*)g_pA16u)
#define G_MV16 ((__nv_bfloat16*)g_Mv16u)
#define G_MA16 ((__nv_bfloat16*)g_Ma16u)

// ---------------- helpers ----------------
__device__ __forceinline__ uint32_t smem_u32(const void* p) {
    uint32_t a;
    asm("{ .reg .u64 t; cvta.to.shared.u64 t, %1; cvt.u32.u64 %0, t; }" : "=r"(a) : "l"(p));
    return a;
}
__device__ __forceinline__ void cp16(uint32_t dst, const void* src) {
    asm volatile("cp.async.cg.shared.global [%0], [%1], 16;" :: "r"(dst), "l"(src) : "memory");
}
__device__ __forceinline__ void cp_commit() {
    asm volatile("cp.async.commit_group;" ::: "memory");
}
__device__ __forceinline__ void cp_wait1() {
    asm volatile("cp.async.wait_group 1;" ::: "memory");
}
__device__ __forceinline__ void cp_wait0() {
    asm volatile("cp.async.wait_group 0;" ::: "memory");
}
__device__ __forceinline__ void ldsm4(uint32_t* r, uint32_t addr) {
    asm volatile("ldmatrix.sync.aligned.m8n8.x4.shared.b16 {%0,%1,%2,%3}, [%4];"
                 : "=r"(r[0]), "=r"(r[1]), "=r"(r[2]), "=r"(r[3]) : "r"(addr));
}
__device__ __forceinline__ void ldsm2(uint32_t* r, uint32_t addr) {
    asm volatile("ldmatrix.sync.aligned.m8n8.x2.shared.b16 {%0,%1}, [%2];"
                 : "=r"(r[0]), "=r"(r[1]) : "r"(addr));
}
__device__ __forceinline__ void mma16816(float* c, const uint32_t* a, const uint32_t* b) {
    asm volatile(
        "mma.sync.aligned.m16n8k16.row.col.f32.bf16.bf16.f32 "
        "{%0,%1,%2,%3}, {%4,%5,%6,%7}, {%8,%9}, {%0,%1,%2,%3};"
        : "+f"(c[0]), "+f"(c[1]), "+f"(c[2]), "+f"(c[3])
        : "r"(a[0]), "r"(a[1]), "r"(a[2]), "r"(a[3]), "r"(b[0]), "r"(b[1]));
}
__device__ __forceinline__ uint2 cvt4(float4 v) {
    __nv_bfloat162 lo = __floats2bfloat162_rn(v.x, v.y);
    __nv_bfloat162 hi = __floats2bfloat162_rn(v.z, v.w);
    uint2 r;
    r.x = *reinterpret_cast<uint32_t*>(&lo);
    r.y = *reinterpret_cast<uint32_t*>(&hi);
    return r;
}

// ---------------------------------------------------------------------------
// Both smooth+cvt passes in ONE launch (R11-validated).
// ---------------------------------------------------------------------------
__global__ void smooth_all_kernel(const float* __restrict__ fvin,
                                  const float* __restrict__ fain)
{
    const int vz = (blockIdx.z == 0);            // z=0: vision, z=1: audio
    const float* f = vz ? fvin : fain;
    const int D = vz ? DV : DA;
    uint2* __restrict__ s16 = reinterpret_cast<uint2*>(vz ? G_SV16 : G_SA16);
    uint2* __restrict__ f16 = reinterpret_cast<uint2*>(vz ? G_FV16 : G_FA16);
    const float4* __restrict__ fv = reinterpret_cast<const float4*>(f);
    const int D4 = D >> 2;
    const long total = (long)NR * D4;
    const float inv3 = 1.0f / 3.0f;
    for (long i = (long)blockIdx.x*blockDim.x + threadIdx.x; i < total;
         i += (long)gridDim.x*blockDim.x) {
        long row = i / D4;
        int s = (int)(row % NS);
        float4 c = fv[i];
        float4 r;
        if (s == 0) {
            float4 n = fv[i + D4];
            r.x=(c.x+n.x)*0.5f; r.y=(c.y+n.y)*0.5f;
            r.z=(c.z+n.z)*0.5f; r.w=(c.w+n.w)*0.5f;
        } else if (s == NS-1) {
            float4 p = fv[i - D4];
            r.x=(c.x+p.x)*0.5f; r.y=(c.y+p.y)*0.5f;
            r.z=(c.z+p.z)*0.5f; r.w=(c.w+p.w)*0.5f;
        } else {
            float4 p = fv[i - D4];
            float4 n = fv[i + D4];
            r.x=(p.x+c.x+n.x)*inv3; r.y=(p.y+c.y+n.y)*inv3;
            r.z=(p.z+c.z+n.z)*inv3; r.w=(p.w+c.w+n.w)*inv3;
        }
        s16[i] = cvt4(r);
        f16[i] = cvt4(c);
    }
}

// ---------------------------------------------------------------------------
// Both M = P @ W GEMMs in ONE launch (R11-validated).
// ---------------------------------------------------------------------------
__global__ void proto_all_kernel(const float* __restrict__ pv,
                                 const float* __restrict__ pa,
                                 const float* __restrict__ wav,
                                 const float* __restrict__ wva)
{
    const int za = (blockIdx.z != 0);
    if (!za && blockIdx.x >= DA/16) return;      // uniform per block, pre-sync
    const float* __restrict__ P = za ? pa : pv;
    const float* __restrict__ W = za ? wva : wav;
    const int D = za ? DA : DV;
    const int C = za ? DV : DA;
    float* __restrict__ Cout = za ? g_Ma : g_Mv;

    __shared__ float As[16][16];
    __shared__ float Ws[16][17];
    int tx = threadIdx.x, ty = threadIdx.y;
    int row = blockIdx.y*16 + ty;
    int col = blockIdx.x*16 + tx;
    float acc = 0.f;
    for (int d0 = 0; d0 < D; d0 += 16) {
        As[ty][tx] = P[row*D + d0 + tx];
        Ws[ty][tx] = W[(d0+ty)*C + col];
        __syncthreads();
        #pragma unroll
        for (int kk = 0; kk < 16; kk++) acc += As[ty][kk]*Ws[kk][tx];
        __syncthreads();
    }
    Cout[row*C + col] = acc;
}

// ---------------------------------------------------------------------------
// All fp32->bf16 conversions in ONE launch (R9-validated).
// ---------------------------------------------------------------------------
__global__ void cvt_all_kernel(const float* __restrict__ pv, const float* __restrict__ pa)
{
    const int nPV = NK*DV, nPA = NK*DA, nMV = NK*DA, nMA = NK*DV;
    const int total = nPV + nPA + nMV + nMA;
    for (int i = blockIdx.x*blockDim.x + threadIdx.x; i < total; i += gridDim.x*blockDim.x) {
        if (i < nPV)                      G_PV16[i] = __float2bfloat16(pv[i]);
        else if (i < nPV+nPA)             G_PA16[i-nPV] = __float2bfloat16(pa[i-nPV]);
        else if (i < nPV+nPA+nMV)         G_MV16[i-nPV-nPA] = __float2bfloat16(g_Mv[i-nPV-nPA]);
        else                              G_MA16[i-nPV-nPA-nMV] = __float2bfloat16(g_Ma[i-nPV-nPA-nMV]);
    }
}

// ---------------------------------------------------------------------------
// Fused HMMA energy kernel. gridDim = (NK/BN, NR/BM, 2).
// R12: split mainloop (static acc arrays -- no runtime accumulator pointer),
// power-of-two stage ring (& 7), exact wait-group discipline.
// Arithmetic identical to R9/R11-validated version.
// ---------------------------------------------------------------------------
extern __shared__ char dsm[];

__global__ __launch_bounds__(NTH)
void fused_energy_kernel()
{
    __shared__ float red_s[8];

    const int tid = threadIdx.x;
    const int wid = tid >> 5;
    const int lane = tid & 31;
    const int z = blockIdx.z;
    const long row0 = (long)blockIdx.y * BM;
    const long col0 = (long)blockIdx.x * BN;

    const __nv_bfloat16 *A1, *B1, *A2, *B2;
    int D1, D2;
    if (z == 0) { A1 = G_FV16; B1 = G_PV16; D1 = DV; A2 = G_SA16; B2 = G_MV16; D2 = DA; }
    else        { A1 = G_FA16; B1 = G_PA16; D1 = DA; A2 = G_SV16; B2 = G_MA16; D2 = DV; }
    const int n1 = D1 / BK;          // 24 or 16, even
    const int nch = n1 + D2 / BK;    // 40

    const uint32_t base0 = smem_u32(dsm);

    auto load_chunk = [&](int c, int stage) {
        const __nv_bfloat16 *A, *B; int D, k0;
        if (c < n1) { A = A1; B = B1; D = D1; k0 = c * BK; }
        else        { A = A2; B = B2; D = D2; k0 = (c - n1) * BK; }
        uint32_t base = base0 + stage * STGB;
        #pragma unroll
        for (int r = 0; r < 2; r++) {
            int u = tid + r * 256;
            int row = u >> 2, seg = u & 3;
            uint32_t d = base + (uint32_t)(row * 80 + seg * 16);
            cp16(d,         A + (row0 + row) * D + k0 + seg * 8);
            cp16(d + ATILE, B + (col0 + row) * D + k0 + seg * 8);
        }
    };
    auto load_pair = [&](int c) {
        load_chunk(c, c & (NSTAGE-1));
        if (c + 1 < nch) load_chunk(c + 1, (c + 1) & (NSTAGE-1));
        cp_commit();
    };

    const int wm = (wid >> 2) * 64;   // warp row base
    const int wn = (wid & 3) * 32;    // warp col base
    const int arow = wm + (lane & 7) + ((lane >> 3) & 1) * 8;
    const int acol = (lane >> 4) * 16;           // byte offset (k-half)
    const int l2 = lane & 15;
    const int brow = wn + (l2 & 7);
    const int bcol = ((l2 >> 3) & 1) * 16;

    // static accumulator reference -> no runtime pointer selection
    auto compute_chunk = [&](int stage, float (&acc)[4][4][4]) {
        uint32_t sA = base0 + stage * STGB;
        uint32_t sB = sA + ATILE;
        #pragma unroll
        for (int ks = 0; ks < 2; ks++) {
            uint32_t a[4][4];
            #pragma unroll
            for (int i = 0; i < 4; i++)
                ldsm4(a[i], sA + (uint32_t)((arow + i * 16) * 80 + acol + ks * 32));
            uint32_t b[4][2];
            #pragma unroll
            for (int j = 0; j < 4; j++)
                ldsm2(b[j], sB + (uint32_t)((brow + j * 8) * 80 + bcol + ks * 32));
            #pragma unroll
            for (int i = 0; i < 4; i++)
                #pragma unroll
                for (int j = 0; j < 4; j++)
                    mma16816(acc[i][j], a[i], b[j]);
        }
    };

    float acc1[4][4][4] = {};
    float acc2[4][4][4] = {};

    load_pair(0);
    load_pair(2);

    // phase 1: chunks [0, n1) -> acc1 (n1 even; pairs never straddle)
    for (int c = 0; c < n1; c += 2) {
        cp_wait1();                      // c+2 < nch always here
        __syncthreads();
        if (c + 4 < nch) load_pair(c + 4);
        compute_chunk(c & (NSTAGE-1), acc1);
        compute_chunk((c + 1) & (NSTAGE-1), acc1);
    }
    // phase 2: chunks [n1, nch) -> acc2
    for (int c = n1; c < nch; c += 2) {
        if (c + 2 < nch) cp_wait1(); else cp_wait0();
        __syncthreads();
        if (c + 4 < nch) load_pair(c + 4);
        compute_chunk(c & (NSTAGE-1), acc2);
        compute_chunk((c + 1) & (NSTAGE-1), acc2);
    }

    float local = 0.f;
    #pragma unroll
    for (int i = 0; i < 4; i++)
        #pragma unroll
        for (int j = 0; j < 4; j++)
            #pragma unroll
            for (int r = 0; r < 4; r++) {
                float c1 = acc1[i][j][r];
                float c2 = acc2[i][j][r];
                float sal = LAM * c2 * c2 + (1.0f - LAM) * c1 * c1;
                float x = sal * c1;
                local += fmaxf(x, 0.f) + log1pf(__expf(-fabsf(x)));
            }
    #pragma unroll
    for (int o = 16; o > 0; o >>= 1)
        local += __shfl_xor_sync(0xFFFFFFFF, local, o);
    if (lane == 0) red_s[wid] = local;
    __syncthreads();
    if (tid == 0) {
        float s = 0.f;
        #pragma unroll
        for (int w = 0; w < 8; w++) s += red_s[w];
        g_partials[(z * gridDim.y + blockIdx.y) * gridDim.x + blockIdx.x] = s;
    }
}

// ---------------------------------------------------------------------------
// Deterministic final reduction
// ---------------------------------------------------------------------------
__global__ void final_reduce_kernel(float* __restrict__ out)
{
    __shared__ double red[256];
    double s = 0.0;
    for (int i = threadIdx.x; i < NBLOCKS; i += 256) s += (double)g_partials[i];
    red[threadIdx.x] = s;
    __syncthreads();
    for (int st = 128; st > 0; st >>= 1) {
        if (threadIdx.x < st) red[threadIdx.x] += red[threadIdx.x + st];
        __syncthreads();
    }
    if (threadIdx.x == 0) out[0] = (float)(-red[0]);
}

// ---------------------------------------------------------------------------
extern "C" void kernel_launch(void* const* d_in, const int* in_sizes, int n_in,
                              void* d_out, int out_size)
{
    const float* fv  = (const float*)d_in[0];   // (8,2048,768)
    const float* fa  = (const float*)d_in[1];   // (8,2048,512)
    const float* pv  = (const float*)d_in[2];   // (512,768)
    const float* pa  = (const float*)d_in[3];   // (512,512)
    const float* wav = (const float*)d_in[4];   // (768,512)
    const float* wva = (const float*)d_in[5];   // (512,768)
    float* out = (float*)d_out;

    cudaFuncSetAttribute(fused_energy_kernel,
                         cudaFuncAttributeMaxDynamicSharedMemorySize, FUSED_SMEM);

    smooth_all_kernel<<<dim3(2048, 1, 2), 256>>>(fv, fa);                         // 0
    proto_all_kernel<<<dim3(DV/16, NK/16, 2), dim3(16,16)>>>(pv, pa, wav, wva);   // 1
    cvt_all_kernel<<<1024, 256>>>(pv, pa);                                        // 2

    fused_energy_kernel<<<dim3(NK/BN, NR/BM, 2), NTH, FUSED_SMEM>>>();            // 3

    final_reduce_kernel<<<1, 256>>>(out);                                         // 4
}